// round 2
// baseline (speedup 1.0000x reference)
#include <cuda_runtime.h>
#include <cuda_bf16.h>

// B=8192, L=1, K=32, H=1024. One CTA per batch row.
// Inputs (metadata order): vals(i32), distances(f32), cache_hidden(f32),
//                          hiddens(f32), W1(f32 64x96), b1(64), W2(1x64), b2(1)
// Output: concat(context_dist_scaled [B*K], new_distances [B*K]) f32.

#define KK 32
#define HH 1024

__global__ __launch_bounds__(256) void mu_kernel(
    const int*   __restrict__ vals,
    const float* __restrict__ distances,
    const float* __restrict__ cache_hidden,
    const float* __restrict__ hiddens,
    const float* __restrict__ W1,
    const float* __restrict__ b1,
    const float* __restrict__ W2,
    const float* __restrict__ b2,
    float* __restrict__ out, int N)
{
    __shared__ float4 sc4[HH / 4];        // cache_hidden row (4 KB)
    __shared__ float  sW1[64 * 97];       // W1 padded stride 97 (conflict-free)
    __shared__ float  sx[96];             // [cd | dist | label_counts]
    __shared__ float  shid[64];

    const int b    = blockIdx.x;
    const int tid  = threadIdx.x;
    const int warp = tid >> 5;
    const int lane = tid & 31;

    // --- stage cache_hidden[b] (1024 f32 = 256 float4, one per thread) ---
    sc4[tid] = ((const float4*)(cache_hidden + (size_t)b * HH))[tid];

    // --- stage W1 into smem, coalesced, rows padded to stride 97 ---
    {
        const float4* g = (const float4*)W1;   // 64*96/4 = 1536 float4
        #pragma unroll
        for (int i = 0; i < 6; i++) {
            int m4 = tid + i * 256;
            float4 v = g[m4];
            int m = m4 * 4;
            int r = m / 96, c = m - r * 96;    // float4 never crosses a row (96%4==0)
            float* d = &sW1[r * 97 + c];
            d[0] = v.x; d[1] = v.y; d[2] = v.z; d[3] = v.w;
        }
    }
    __syncthreads();

    // --- cdist: each warp handles 4 of the 32 k-rows ---
    const float4* H4 = (const float4*)(hiddens + (size_t)b * KK * HH);
    #pragma unroll
    for (int kk = 0; kk < 4; kk++) {
        int k = warp * 4 + kk;
        float acc = 0.f;
        #pragma unroll
        for (int it = 0; it < 8; it++) {
            int idx = it * 32 + lane;                  // coalesced 512B per step
            float4 x = __ldcs(&H4[k * 256 + idx]);     // streaming: evict-first
            float4 c = sc4[idx];
            float dx = c.x - x.x, dy = c.y - x.y, dz = c.z - x.z, dw = c.w - x.w;
            acc += dx * dx + dy * dy + dz * dz + dw * dw;
        }
        #pragma unroll
        for (int o = 16; o; o >>= 1) acc += __shfl_xor_sync(0xffffffffu, acc, o);
        if (lane == 0) sx[k] = sqrtf(acc);
    }

    // --- warp 0: distances + label counts (distinct nonzero prefix counts) ---
    if (warp == 0) {
        sx[32 + lane] = distances[b * KK + lane];
        int v = vals[b * KK + lane];
        unsigned m = __match_any_sync(0xffffffffu, v);
        int isnew = (v != 0) && ((m & ((1u << lane) - 1u)) == 0);
        int cnt = isnew;
        #pragma unroll
        for (int o = 1; o < 32; o <<= 1) {
            int t = __shfl_up_sync(0xffffffffu, cnt, o);
            if (lane >= o) cnt += t;
        }
        sx[64 + lane] = (float)cnt;
    }
    __syncthreads();

    // --- MLP layer 1: 64 threads, one neuron each ---
    if (tid < 64) {
        float acc = b1[tid];
        const float* w = &sW1[tid * 97];
        #pragma unroll
        for (int i = 0; i < 96; i++) acc += sx[i] * w[i];
        shid[tid] = tanhf(acc);
    }
    __syncthreads();

    // --- warp 0: layer 2 + sigmoid + scale + write outputs ---
    if (warp == 0) {
        float s = shid[lane] * W2[lane] + shid[lane + 32] * W2[lane + 32];
        #pragma unroll
        for (int o = 16; o; o >>= 1) s += __shfl_xor_sync(0xffffffffu, s, o);
        s += b2[0];
        float mu = 1.f / (1.f + expf(-s));
        float scale = __shfl_sync(0xffffffffu, 5.f * mu, 0);
        float cd = sx[lane] * scale;
        int o0 = b * KK + lane;
        out[o0]     = cd;
        out[N + o0] = sx[32 + lane] + cd;
    }
}

extern "C" void kernel_launch(void* const* d_in, const int* in_sizes, int n_in,
                              void* d_out, int out_size)
{
    const int*   vals         = (const int*)  d_in[0];
    const float* distances    = (const float*)d_in[1];
    const float* cache_hidden = (const float*)d_in[2];
    const float* hiddens      = (const float*)d_in[3];
    const float* W1           = (const float*)d_in[4];
    const float* b1           = (const float*)d_in[5];
    const float* W2           = (const float*)d_in[6];
    const float* b2           = (const float*)d_in[7];
    float* out = (float*)d_out;

    int N = in_sizes[1];              // B*L*K = 262144
    int B = N / KK;                   // 8192

    mu_kernel<<<B, 256>>>(vals, distances, cache_hidden, hiddens,
                          W1, b1, W2, b2, out, N);
}

// round 3
// speedup vs baseline: 1.0227x; 1.0227x over previous
#include <cuda_runtime.h>
#include <cuda_bf16.h>

// B=8192, L=1, K=32, H=1024. One CTA per batch row, 8 warps.
// Each warp owns 4 k-rows, processed as 4 interleaved accumulator streams
// so 4 independent LDG.128 are in flight per loop step (no issue gaps).
// W1 is read directly from gmem in the MLP tail (L1-resident per SM),
// not staged to smem — saves 24KB smem + ~200MB of L2 restage traffic.

#define KK 32
#define HH 1024

__global__ __launch_bounds__(256, 6) void mu_kernel(
    const int*   __restrict__ vals,
    const float* __restrict__ distances,
    const float* __restrict__ cache_hidden,
    const float* __restrict__ hiddens,
    const float* __restrict__ W1,
    const float* __restrict__ b1,
    const float* __restrict__ W2,
    const float* __restrict__ b2,
    float* __restrict__ out, int N)
{
    __shared__ float4 sc4[HH / 4];                 // cache_hidden row (4 KB)
    __shared__ __align__(16) float sx[96];         // [cd | dist | label_counts]
    __shared__ float shid[64];

    const int b    = blockIdx.x;
    const int tid  = threadIdx.x;
    const int warp = tid >> 5;
    const int lane = tid & 31;

    // stage cache_hidden[b] (1024 f32 = 256 float4, one per thread)
    sc4[tid] = ((const float4*)(cache_hidden + (size_t)b * HH))[tid];
    __syncthreads();

    // --- cdist: 4 interleaved k-streams per warp ---
    const float4* H4 = (const float4*)(hiddens + (size_t)b * KK * HH);
    const int kbase = warp * 4;
    const float4* r0 = &H4[(kbase + 0) * 256];
    const float4* r1 = &H4[(kbase + 1) * 256];
    const float4* r2 = &H4[(kbase + 2) * 256];
    const float4* r3 = &H4[(kbase + 3) * 256];

    float a0 = 0.f, a1 = 0.f, a2 = 0.f, a3 = 0.f;
    #pragma unroll
    for (int it = 0; it < 8; it++) {
        int idx = it * 32 + lane;                  // coalesced 512B per LDG
        float4 c = sc4[idx];
        float4 x0 = __ldcs(&r0[idx]);
        float4 x1 = __ldcs(&r1[idx]);
        float4 x2 = __ldcs(&r2[idx]);
        float4 x3 = __ldcs(&r3[idx]);
        float d;
        d = c.x - x0.x; a0 += d * d;  d = c.y - x0.y; a0 += d * d;
        d = c.z - x0.z; a0 += d * d;  d = c.w - x0.w; a0 += d * d;
        d = c.x - x1.x; a1 += d * d;  d = c.y - x1.y; a1 += d * d;
        d = c.z - x1.z; a1 += d * d;  d = c.w - x1.w; a1 += d * d;
        d = c.x - x2.x; a2 += d * d;  d = c.y - x2.y; a2 += d * d;
        d = c.z - x2.z; a2 += d * d;  d = c.w - x2.w; a2 += d * d;
        d = c.x - x3.x; a3 += d * d;  d = c.y - x3.y; a3 += d * d;
        d = c.z - x3.z; a3 += d * d;  d = c.w - x3.w; a3 += d * d;
    }
    // one reduction drain per warp (4 butterflies)
    #pragma unroll
    for (int o = 16; o; o >>= 1) {
        a0 += __shfl_xor_sync(0xffffffffu, a0, o);
        a1 += __shfl_xor_sync(0xffffffffu, a1, o);
        a2 += __shfl_xor_sync(0xffffffffu, a2, o);
        a3 += __shfl_xor_sync(0xffffffffu, a3, o);
    }
    if (lane == 0) {
        sx[kbase + 0] = sqrtf(a0);
        sx[kbase + 1] = sqrtf(a1);
        sx[kbase + 2] = sqrtf(a2);
        sx[kbase + 3] = sqrtf(a3);
    }

    // --- warp 0: distances + distinct-nonzero prefix counts ---
    if (warp == 0) {
        sx[32 + lane] = distances[b * KK + lane];
        int v = vals[b * KK + lane];
        unsigned m = __match_any_sync(0xffffffffu, v);
        int isnew = (v != 0) && ((m & ((1u << lane) - 1u)) == 0);
        int cnt = isnew;
        #pragma unroll
        for (int o = 1; o < 32; o <<= 1) {
            int t = __shfl_up_sync(0xffffffffu, cnt, o);
            if (lane >= o) cnt += t;
        }
        sx[64 + lane] = (float)cnt;
    }
    __syncthreads();

    // --- MLP layer 1: 64 threads, W1 straight from gmem (L1-resident) ---
    if (tid < 64) {
        const float4* w4 = (const float4*)(W1 + tid * 96);
        const float4* x4 = (const float4*)sx;
        float acc = __ldg(&b1[tid]);
        #pragma unroll
        for (int i = 0; i < 24; i++) {
            float4 w = __ldg(&w4[i]);
            float4 x = x4[i];
            acc += w.x * x.x + w.y * x.y + w.z * x.z + w.w * x.w;
        }
        shid[tid] = tanhf(acc);
    }
    __syncthreads();

    // --- warp 0: layer 2 + sigmoid + scale + write ---
    if (warp == 0) {
        float s = shid[lane] * __ldg(&W2[lane])
                + shid[lane + 32] * __ldg(&W2[lane + 32]);
        #pragma unroll
        for (int o = 16; o; o >>= 1) s += __shfl_xor_sync(0xffffffffu, s, o);
        s += __ldg(&b2[0]);
        float mu = 1.f / (1.f + expf(-s));
        float scale = __shfl_sync(0xffffffffu, 5.f * mu, 0);
        float cd = sx[lane] * scale;
        int o0 = b * KK + lane;
        out[o0]     = cd;
        out[N + o0] = sx[32 + lane] + cd;
    }
}

extern "C" void kernel_launch(void* const* d_in, const int* in_sizes, int n_in,
                              void* d_out, int out_size)
{
    const int*   vals         = (const int*)  d_in[0];
    const float* distances    = (const float*)d_in[1];
    const float* cache_hidden = (const float*)d_in[2];
    const float* hiddens      = (const float*)d_in[3];
    const float* W1           = (const float*)d_in[4];
    const float* b1           = (const float*)d_in[5];
    const float* W2           = (const float*)d_in[6];
    const float* b2           = (const float*)d_in[7];
    float* out = (float*)d_out;

    int N = in_sizes[1];              // B*L*K = 262144
    int B = N / KK;                   // 8192

    mu_kernel<<<B, 256>>>(vals, distances, cache_hidden, hiddens,
                          W1, b1, W2, b2, out, N);
}